// round 14
// baseline (speedup 1.0000x reference)
#include <cuda_runtime.h>
#include <cuda_fp16.h>

// WOS filter: fp16x2-packed bisection (with deterministic safety margins)
// + exact f32 fused upward walk.
// f(t) = sum_j w_j * [mx_j >= t]. answer = min{mx_e : f(mx_e) <= B}, else max(mx).
// fp16 bisection only STEERS the bracket:
//   - lo=mid only when F_fp16(mid) > B + EPS  (EPS >> fp16 sum error ~0.07)
//     => F_exact_strict(mid - DELTA) > B deterministically (DELTA > 2*fp16 ulp(|mx|))
//   - walk starts at lo - DELTA, evaluates candidates EXACTLY in f32
//   - wrongly-feasible hi only adds walk hops (walk is upward-unbounded + exact)
#define NCH   8
#define MD    54
#define HMD   27
#define HH    160
#define WW    160
#define HO    158
#define WO    158
#define LPIX  (HO * WO)
#define NPIX  (4 * LPIX)
#define BITER 8
#define MAXHOP 8
#define EPS   0.25f
#define DELTA 0.02f

__global__ __launch_bounds__(128, 4) void WOS_72842645340328_kernel(
    const float* __restrict__ x,
    const float* __restrict__ weight,
    const float* __restrict__ bias,
    const float* __restrict__ mask,
    float* __restrict__ out)
{
    const int c = blockIdx.y;                       // warp-uniform channel
    const int n = blockIdx.x * 128 + threadIdx.x;   // pixel task id
    if (n >= NPIX) return;

    int b  = n / LPIX;
    int l  = n - b * LPIX;
    int ho = l / WO;
    int wo = l - ho * WO;

    // Per-channel constants -> uniform registers
    const float* wt = weight + c * MD;
    const float* mk = mask   + c * MD;
    float w[MD];
#pragma unroll
    for (int j = 0; j < MD; ++j) w[j] = wt[j];
    float mkr[MD];
#pragma unroll
    for (int j = 0; j < MD; ++j) mkr[j] = mk[j];
    const float Bc = bias[c];

    const float* xb = x + ((b * 3) * HH + ho) * WW + wo;

    // Gather + mx build with fused max(|mx|) tracking
    float mx[MD];
    float M0, M1;
    {
        float v0 = __ldg(xb);
        mx[0]  = v0 + mkr[0];
        mx[27] = mkr[27] - v0;
        M0 = fabsf(mx[0]);
        M1 = fabsf(mx[27]);
    }
#pragma unroll
    for (int ch = 0; ch < 3; ++ch)
#pragma unroll
        for (int kh = 0; kh < 3; ++kh)
#pragma unroll
            for (int kw = 0; kw < 3; ++kw) {
                int d = ch * 9 + kh * 3 + kw;
                if (d == 0) continue;
                float v = __ldg(xb + (ch * HH + kh) * WW + kw);
                float p = v + mkr[d];
                float q = mkr[27 + d] - v;
                mx[d]      = p;
                mx[27 + d] = q;
                M0 = fmaxf(M0, fabsf(p));
                M1 = fmaxf(M1, fabsf(q));
            }
    float M  = fmaxf(M0, M1);
    float lo = -M - 0.01f;    // strictly below all elements
    float hi = M;

    // Pack mx and (uniform) weights to half2
    half2 hx[HMD];
#pragma unroll
    for (int k = 0; k < HMD; ++k) hx[k] = __floats2half2_rn(mx[2 * k], mx[2 * k + 1]);
    half2 hw[HMD];
#pragma unroll
    for (int k = 0; k < HMD; ++k) hw[k] = __floats2half2_rn(w[2 * k], w[2 * k + 1]);

    const float BcEps = Bc + EPS;

    // fp16 bisection (3 independent HFMA2 chains for ILP)
#pragma unroll
    for (int it = 0; it < BITER; ++it) {
        float mid = 0.5f * (lo + hi);
        half2 hmid = __float2half2_rn(mid);
        half2 acc0 = __float2half2_rn(0.f);
        half2 acc1 = acc0, acc2 = acc0;
#pragma unroll
        for (int k = 0; k < HMD; k += 3) {
            acc0 = __hfma2(__hgt2(hx[k],     hmid), hw[k],     acc0);
            acc1 = __hfma2(__hgt2(hx[k + 1], hmid), hw[k + 1], acc1);
            acc2 = __hfma2(__hgt2(hx[k + 2], hmid), hw[k + 2], acc2);
        }
        half2 acc = __hadd2(__hadd2(acc0, acc1), acc2);
        float F = __low2float(acc) + __high2float(acc);
        if (F <= BcEps) hi = mid; else lo = mid;
    }

    lo -= DELTA;   // cover fp16 rounding of comparisons deterministically

    const float INF = __int_as_float(0x7f800000);

    // Walk pass 1 (slim, exact f32): cand1 = min{mx > lo}; exists and is
    // infeasible because F_exact_strict(lo) > B (margin construction).
    float a;
    {
        float c0 = INF, c1 = INF;
#pragma unroll
        for (int j = 0; j < MD; j += 2) {
            if (mx[j]     > lo) c0 = fminf(c0, mx[j]);
            if (mx[j + 1] > lo) c1 = fminf(c1, mx[j + 1]);
        }
        a = fminf(c0, c1);
    }
    float prev = a;
    float ans  = a;
    bool  done = false;

    // Walk passes 2+: fused cand + exact F (f32)
#pragma unroll 1
    for (int it = 0; it < MAXHOP; ++it) {
        if (__all_sync(0xffffffffu, done)) break;
        if (!done) {
            float c0 = INF, c1 = INF;
            float s0 = 0.f, s1 = 0.f, s2 = 0.f, s3 = 0.f;
#pragma unroll
            for (int j = 0; j + 3 < MD; j += 4) {
                bool p0 = mx[j]     > a;
                bool p1 = mx[j + 1] > a;
                bool p2 = mx[j + 2] > a;
                bool p3 = mx[j + 3] > a;
                if (p0) { c0 = fminf(c0, mx[j]);     s0 += w[j];     }
                if (p1) { c1 = fminf(c1, mx[j + 1]); s1 += w[j + 1]; }
                if (p2) { c0 = fminf(c0, mx[j + 2]); s2 += w[j + 2]; }
                if (p3) { c1 = fminf(c1, mx[j + 3]); s3 += w[j + 3]; }
            }
            {   // tail 52, 53
                bool p0 = mx[52] > a;
                bool p1 = mx[53] > a;
                if (p0) { c0 = fminf(c0, mx[52]); s0 += w[52]; }
                if (p1) { c1 = fminf(c1, mx[53]); s1 += w[53]; }
            }
            float cand = fminf(c0, c1);
            float F = (s0 + s1) + (s2 + s3);

            if (cand > 3.0e38f) {        // walked past max element: clip-to-max
                ans = prev; done = true;
            } else if (F <= Bc) {        // F = f(cand) exactly; first feasible wins
                ans = cand; done = true;
            } else {
                ans = cand; prev = cand; a = cand;
            }
        }
    }

    out[n * NCH + c] = ans;
}

extern "C" void kernel_launch(void* const* d_in, const int* in_sizes, int n_in,
                              void* d_out, int out_size)
{
    const float* x      = (const float*)d_in[0];
    const float* weight = (const float*)d_in[1];
    const float* bias   = (const float*)d_in[2];
    const float* mask   = (const float*)d_in[3];
    float* out = (float*)d_out;

    dim3 grid((NPIX + 127) / 128, NCH);
    WOS_72842645340328_kernel<<<grid, 128>>>(x, weight, bias, mask, out);
}